// round 5
// baseline (speedup 1.0000x reference)
#include <cuda_runtime.h>
#include <math.h>

#define NB   8
#define C    128
#define H    56
#define W    56
#define O    64
#define NC   2
#define KS   5
#define P    25
#define P2   50           // NC * P
#define HW   (H * W)      // 3136
#define PIX  (NB * HW)    // 25088
#define CP   (C * P)      // 3200  (Wt inner size per o)

typedef unsigned long long u64;

// Scratch (allocation-free rule: __device__ globals)
__device__ __align__(16) float g_V[P2 * C];  // folded weights V[p2][c]
__device__ float g_const[NC];                // per-class constant
__device__ float g_Y[NB * P * HW * 2];       // Y[n][p][hw][{class0,class1}]

__device__ __forceinline__ void fma2(u64& d, u64 a, u64 b) {
    asm("fma.rn.f32x2 %0, %1, %2, %0;" : "+l"(d) : "l"(a), "l"(b));
}
__device__ __forceinline__ u64 pack2(float lo, float hi) {
    u64 r;
    asm("mov.b64 %0, {%1, %2};" : "=l"(r) : "f"(lo), "f"(hi));
    return r;
}
__device__ __forceinline__ float hadd2(u64 v) {
    float lo, hi;
    asm("mov.b64 {%0, %1}, %2;" : "=f"(lo), "=f"(hi) : "l"(v));
    return lo + hi;
}

// ---------------------------------------------------------------------------
// Kernel 1: V = Wlin(2x64) @ Wt(64x3200), fully coalesced over the 3200 dim.
// ---------------------------------------------------------------------------
__global__ void prep_kernel(const float* __restrict__ Wt,
                            const float* __restrict__ bias,
                            const float* __restrict__ Wlin,
                            const float* __restrict__ blin) {
    int j = blockIdx.x * blockDim.x + threadIdx.x;   // 0..3199 = c*25 + p
    if (j < CP) {
        float s0 = 0.f, s1 = 0.f;
        #pragma unroll
        for (int o = 0; o < O; o++) {
            float w = Wt[o * CP + j];                 // coalesced across lanes
            s0 = fmaf(__ldg(&Wlin[o]),     w, s0);
            s1 = fmaf(__ldg(&Wlin[O + o]), w, s1);
        }
        int c = j / P, p = j % P;
        g_V[p * C + c]       = s0;                    // p2 = p       (class 0)
        g_V[(P + p) * C + c] = s1;                    // p2 = 25 + p  (class 1)
    }
    if (j < NC) {
        float s = blin[j];
        #pragma unroll
        for (int o = 0; o < O; o++) s += bias[o] * Wlin[j * O + o];
        g_const[j] = s;
    }
}

// ---------------------------------------------------------------------------
// Kernel 2: pointwise projection, packed f32x2 over channel pairs.
// acc[p2] accumulates (even-channel partial, odd-channel partial);
// weight pairs (c,c+1) come straight out of shared as b64 — no replication.
// ---------------------------------------------------------------------------
__global__ void __launch_bounds__(128) proj_kernel(const float* __restrict__ x) {
    __shared__ __align__(16) float sV[P2 * C];        // 25.6 KB
    for (int i = threadIdx.x; i < P2 * C / 4; i += blockDim.x)
        reinterpret_cast<float4*>(sV)[i] = reinterpret_cast<const float4*>(g_V)[i];
    __syncthreads();

    int pix = blockIdx.x * 128 + threadIdx.x;         // grid exact: pix < PIX
    int n  = pix / HW;
    int hw = pix % HW;
    const float* xb = x + (size_t)n * C * HW + hw;

    u64 acc[P2];
    #pragma unroll
    for (int p = 0; p < P2; p++) acc[p] = 0ull;

    const ulonglong2* sV2 = reinterpret_cast<const ulonglong2*>(sV);

    #pragma unroll 2
    for (int c4 = 0; c4 < C / 4; c4++) {
        float x0 = xb[(c4 * 4 + 0) * HW];
        float x1 = xb[(c4 * 4 + 1) * HW];
        float x2 = xb[(c4 * 4 + 2) * HW];
        float x3 = xb[(c4 * 4 + 3) * HW];
        u64 xp01 = pack2(x0, x1);
        u64 xp23 = pack2(x2, x3);
        #pragma unroll
        for (int p = 0; p < P2; p++) {
            ulonglong2 wv = sV2[p * (C / 4) + c4];    // LDS.128: 2 packed pairs
            fma2(acc[p], wv.x, xp01);
            fma2(acc[p], wv.y, xp23);
        }
    }

    // horizontal add + class-interleaved store: Y[n][p][hw][2]
    float2* yb = reinterpret_cast<float2*>(g_Y) + (size_t)n * P * HW + hw;
    #pragma unroll
    for (int p = 0; p < P; p++) {
        float2 v;
        v.x = hadd2(acc[p]);
        v.y = hadd2(acc[P + p]);
        yb[p * HW] = v;
    }
}

// ---------------------------------------------------------------------------
// Kernel 3: 5x5 spatial gather (one LDG.64 per tap) + drift/exp epilogue.
// ---------------------------------------------------------------------------
__global__ void __launch_bounds__(256) final_kernel(float* __restrict__ out) {
    int pix = blockIdx.x * blockDim.x + threadIdx.x;
    if (pix >= PIX) return;
    int n  = pix / HW;
    int hw = pix % HW;
    int h  = hw / W;
    int w  = hw % W;

    const float2* yb = reinterpret_cast<const float2*>(g_Y) + (size_t)n * P * HW;
    float c0 = g_const[0], c1 = g_const[1];

    float sum0 = 0.f, sum1 = 0.f;
    float as0 = 0.f, as1 = 0.f;
    float ys0 = 0.f, ys1 = 0.f;
    float xs0 = 0.f, xs1 = 0.f;

    #pragma unroll
    for (int i = 0; i < KS; i++) {
        int hh = h + i - 2;
        bool hin = (hh >= 0) && (hh < H);
        #pragma unroll
        for (int j = 0; j < KS; j++) {
            int ww = w + j - 2;
            bool in = hin && (ww >= 0) && (ww < W);
            int p = i * KS + j;
            float2 v = make_float2(0.f, 0.f);
            if (in) v = yb[p * HW + hh * W + ww];
            float m0 = v.x + c0, m1 = v.y + c1;
            float a0 = fabsf(m0), a1 = fabsf(m1);
            float yo = (float)(i - 2), xo = (float)(j - 2);
            sum0 += m0;      sum1 += m1;
            as0  += a0;      as1  += a1;
            ys0  = fmaf(a0, yo, ys0);  ys1 = fmaf(a1, yo, ys1);
            xs0  = fmaf(a0, xo, xs0);  xs1 = fmaf(a1, xo, xs1);
        }
    }

    float yd0 = ys0 / as0, xd0 = xs0 / as0;
    float yd1 = ys1 / as1, xd1 = xs1 / as1;
    float d0 = sqrtf(fmaf(xd0, xd0, yd0 * yd0));
    float d1 = sqrtf(fmaf(xd1, xd1, yd1 * yd1));
    out[pix * 2 + 0] = sum0 * expf(-0.5f * d0);
    out[pix * 2 + 1] = sum1 * expf(-0.5f * d1);
}

// ---------------------------------------------------------------------------
extern "C" void kernel_launch(void* const* d_in, const int* in_sizes, int n_in,
                              void* d_out, int out_size) {
    const float* x    = (const float*)d_in[0];  // (8,128,56,56)
    const float* Wt   = (const float*)d_in[1];  // (64,128,5,5)
    const float* bias = (const float*)d_in[2];  // (64,)
    const float* Wlin = (const float*)d_in[3];  // (2,64)
    const float* blin = (const float*)d_in[4];  // (2,)
    float* out = (float*)d_out;                 // (8,56,56,2)

    prep_kernel<<<(CP + 127) / 128, 128>>>(Wt, bias, Wlin, blin);
    proj_kernel<<<PIX / 128, 128>>>(x);         // 196 blocks, exact
    final_kernel<<<(PIX + 255) / 256, 256>>>(out);
}